// round 6
// baseline (speedup 1.0000x reference)
#include <cuda_runtime.h>
#include <cuda_bf16.h>

#define NB  16
#define NT  512
#define ND  384
#define RPB 64           // output rows (positions) per block

// Fused kernel: per-block redundant scan of this batch's 512 durations,
// smem inverse-map scatter for this block's RPB positions, then gather-copy.
__global__ __launch_bounds__(256) void lr_fused_kernel(const float* __restrict__ enc,
                                                       const int* __restrict__ dur,
                                                       float* __restrict__ out,
                                                       float* __restrict__ out_tail,
                                                       int has_tail, int max_len,
                                                       int nchunks) {
    __shared__ int s_wsum[8];       // per-warp pair-sum totals
    __shared__ int s_wexcl[8];      // exclusive warp offsets
    __shared__ int s_tok[RPB];      // token index per local position, -1 => zero row

    const int blk   = blockIdx.x;
    const int b     = blk / nchunks;
    const int chunk = blk - b * nchunks;
    const int cs    = chunk * RPB;
    const int ce    = min(cs + RPB, max_len);

    const int tid  = threadIdx.x;
    const int wid  = tid >> 5;
    const int lane = tid & 31;

    // ---- scan: each thread owns tokens 2*tid, 2*tid+1 ----
    const int2 d2 = ((const int2*)(dur + b * NT))[tid];
    int x = d2.x + d2.y;                      // pair sum
    #pragma unroll
    for (int off = 1; off < 32; off <<= 1) {
        int y = __shfl_up_sync(0xffffffffu, x, off);
        if (lane >= off) x += y;
    }
    if (lane == 31) s_wsum[wid] = x;

    // init smem tok to -1 while waiting
    if (tid < RPB) s_tok[tid] = -1;
    __syncthreads();

    if (wid == 0 && lane < 8) {
        int w = s_wsum[lane];
        int v = w;
        #pragma unroll
        for (int off = 1; off < 8; off <<= 1) {
            int y = __shfl_up_sync(0x000000ffu, v, off);
            if (lane >= off) v += y;
        }
        s_wexcl[lane] = v - w;                // exclusive warp offset
        if (lane == 7) s_wsum[0] = v;         // grand total (mel) reused slot
    }
    __syncthreads();

    const int incl1 = s_wexcl[wid] + x;       // cumsum after token 2*tid+1
    const int incl0 = incl1 - d2.y;           // cumsum after token 2*tid
    const int excl0 = incl0 - d2.x;           // before token 2*tid
    const int mel   = s_wsum[0];

    if (has_tail && chunk == 0 && tid == 0) out_tail[b] = (float)mel;

    // ---- scatter inverse map restricted to [cs, ce) ----
    {
        int lo = max(excl0, cs), hi = min(min(incl0, max_len), ce);
        for (int p = lo; p < hi; ++p) s_tok[p - cs] = 2 * tid;
        lo = max(incl0, cs); hi = min(min(incl1, max_len), ce);
        for (int p = lo; p < hi; ++p) s_tok[p - cs] = 2 * tid + 1;
    }
    __syncthreads();

    // ---- gather-copy: 8 warps x 8 rows each (4 iterations of 2 rows) ----
    const float4* base = (const float4*)(enc + (size_t)b * NT * ND);
    const float4  z    = make_float4(0.f, 0.f, 0.f, 0.f);

    const int rbase = wid * (RPB / 8);        // this warp's first local row

    // Hoist all tok loads (independent LDS, broadcast) before the copy chain.
    int2 tk[4];
    #pragma unroll
    for (int it = 0; it < 4; ++it)
        tk[it] = *(const int2*)&s_tok[rbase + it * 2];

    #pragma unroll
    for (int it = 0; it < 4; ++it) {
        const int pos = cs + rbase + it * 2;  // even global position
        if (pos >= max_len) break;
        const bool have1 = (pos + 1 < max_len);

        float4 v0a = z, v0b = z, v0c = z;
        float4 v1a = z, v1b = z, v1c = z;

        if (tk[it].x >= 0) {
            const float4* s0 = base + (size_t)tk[it].x * (ND / 4);
            v0a = s0[lane]; v0b = s0[lane + 32]; v0c = s0[lane + 64];
        }
        if (have1 && tk[it].y >= 0) {
            const float4* s1 = base + (size_t)tk[it].y * (ND / 4);
            v1a = s1[lane]; v1b = s1[lane + 32]; v1c = s1[lane + 64];
        }

        float4* d0 = (float4*)(out + ((size_t)b * max_len + pos) * ND);
        d0[lane] = v0a; d0[lane + 32] = v0b; d0[lane + 64] = v0c;
        if (have1) {
            float4* d1 = d0 + (ND / 4);
            d1[lane] = v1a; d1[lane + 32] = v1b; d1[lane + 64] = v1c;
        }
    }
}

// Zero-fill residual tail elements beyond the B mel_lens slots (defensive).
__global__ void fill_zero_kernel(float* __restrict__ p, long long n) {
    long long i = (long long)blockIdx.x * blockDim.x + threadIdx.x;
    if (i < n) p[i] = 0.f;
}

extern "C" void kernel_launch(void* const* d_in, const int* in_sizes, int n_in,
                              void* d_out, int out_size) {
    const float* enc = (const float*)d_in[0];
    const int*   dur = (const int*)d_in[1];
    float* out = (float*)d_out;

    // Derive max_len from out_size: out = [B, max_len, D] floats (+ B mel_lens tail).
    const long long row_elems = (long long)NB * ND;   // 6144
    long long total = (long long)out_size;
    int max_len;
    long long tail_elems;
    if (total % row_elems == 0) {
        max_len = (int)(total / row_elems);
        tail_elems = 0;
    } else {
        tail_elems = total % row_elems;                // typically == NB
        max_len = (int)((total - tail_elems) / row_elems);
    }

    const long long body = (long long)NB * max_len * ND;
    float* tail = out + body;

    const int nchunks = (max_len + RPB - 1) / RPB;
    lr_fused_kernel<<<NB * nchunks, 256>>>(enc, dur, out, tail,
                                           tail_elems >= NB ? 1 : 0, max_len, nchunks);

    if (tail_elems > NB) {
        long long rem = tail_elems - NB;
        fill_zero_kernel<<<(int)((rem + 255) / 256), 256>>>(tail + NB, rem);
    }
}

// round 7
// speedup vs baseline: 1.0206x; 1.0206x over previous
#include <cuda_runtime.h>
#include <cuda_bf16.h>

#define NB  16
#define NT  512
#define ND  384
#define RPB 64           // output rows (positions) per block

// Fused kernel: per-block redundant scan of this batch's 512 durations,
// smem inverse-map scatter for this block's RPB positions, then gather-copy.
__global__ __launch_bounds__(256, 8) void lr_fused_kernel(const float* __restrict__ enc,
                                                          const int* __restrict__ dur,
                                                          float* __restrict__ out,
                                                          float* __restrict__ out_tail,
                                                          int has_tail, int max_len,
                                                          int nchunks) {
    __shared__ int s_wsum[8];       // per-warp pair-sum totals
    __shared__ int s_wexcl[8];      // exclusive warp offsets
    __shared__ int s_tok[RPB];      // token index per local position, -1 => zero row

    const int blk   = blockIdx.x;
    const int b     = blk / nchunks;
    const int chunk = blk - b * nchunks;
    const int cs    = chunk * RPB;
    const int ce    = min(cs + RPB, max_len);

    const int tid  = threadIdx.x;
    const int wid  = tid >> 5;
    const int lane = tid & 31;

    // ---- scan: each thread owns tokens 2*tid, 2*tid+1 ----
    const int2 d2 = ((const int2*)(dur + b * NT))[tid];
    int x = d2.x + d2.y;                      // pair sum
    #pragma unroll
    for (int off = 1; off < 32; off <<= 1) {
        int y = __shfl_up_sync(0xffffffffu, x, off);
        if (lane >= off) x += y;
    }
    if (lane == 31) s_wsum[wid] = x;

    // init smem tok to -1 while waiting
    if (tid < RPB) s_tok[tid] = -1;
    __syncthreads();

    if (wid == 0 && lane < 8) {
        int w = s_wsum[lane];
        int v = w;
        #pragma unroll
        for (int off = 1; off < 8; off <<= 1) {
            int y = __shfl_up_sync(0x000000ffu, v, off);
            if (lane >= off) v += y;
        }
        s_wexcl[lane] = v - w;                // exclusive warp offset
        if (lane == 7) s_wsum[0] = v;         // grand total (mel) reused slot
    }
    __syncthreads();

    const int incl1 = s_wexcl[wid] + x;       // cumsum after token 2*tid+1
    const int incl0 = incl1 - d2.y;           // cumsum after token 2*tid
    const int excl0 = incl0 - d2.x;           // before token 2*tid
    const int mel   = s_wsum[0];

    if (has_tail && chunk == 0 && tid == 0) out_tail[b] = (float)mel;

    // ---- scatter inverse map restricted to [cs, ce) ----
    {
        int lo = max(excl0, cs), hi = min(min(incl0, max_len), ce);
        for (int p = lo; p < hi; ++p) s_tok[p - cs] = 2 * tid;
        lo = max(incl0, cs); hi = min(min(incl1, max_len), ce);
        for (int p = lo; p < hi; ++p) s_tok[p - cs] = 2 * tid + 1;
    }
    __syncthreads();

    // ---- gather-copy: 8 warps x 8 rows each, one row per iteration ----
    const float4* base = (const float4*)(enc + (size_t)b * NT * ND);
    const int rbase = wid * (RPB / 8);        // this warp's first local row
    float4* dst = (float4*)(out + ((size_t)b * max_len + cs + rbase) * ND);

    #pragma unroll
    for (int it = 0; it < 8; ++it) {
        const int pos = cs + rbase + it;
        if (pos >= max_len) break;

        const int tok = s_tok[rbase + it];    // LDS broadcast

        float4 va = make_float4(0.f, 0.f, 0.f, 0.f);
        float4 vb = va, vc = va;
        if (tok >= 0) {                       // predicated LDGs
            const float4* s0 = base + (size_t)tok * (ND / 4);
            va = s0[lane]; vb = s0[lane + 32]; vc = s0[lane + 64];
        }

        float4* d0 = dst + (size_t)it * (ND / 4);
        d0[lane] = va; d0[lane + 32] = vb; d0[lane + 64] = vc;
    }
}

// Zero-fill residual tail elements beyond the B mel_lens slots (defensive).
__global__ void fill_zero_kernel(float* __restrict__ p, long long n) {
    long long i = (long long)blockIdx.x * blockDim.x + threadIdx.x;
    if (i < n) p[i] = 0.f;
}

extern "C" void kernel_launch(void* const* d_in, const int* in_sizes, int n_in,
                              void* d_out, int out_size) {
    const float* enc = (const float*)d_in[0];
    const int*   dur = (const int*)d_in[1];
    float* out = (float*)d_out;

    // Derive max_len from out_size: out = [B, max_len, D] floats (+ B mel_lens tail).
    const long long row_elems = (long long)NB * ND;   // 6144
    long long total = (long long)out_size;
    int max_len;
    long long tail_elems;
    if (total % row_elems == 0) {
        max_len = (int)(total / row_elems);
        tail_elems = 0;
    } else {
        tail_elems = total % row_elems;                // typically == NB
        max_len = (int)((total - tail_elems) / row_elems);
    }

    const long long body = (long long)NB * max_len * ND;
    float* tail = out + body;

    const int nchunks = (max_len + RPB - 1) / RPB;
    lr_fused_kernel<<<NB * nchunks, 256>>>(enc, dur, out, tail,
                                           tail_elems >= NB ? 1 : 0, max_len, nchunks);

    if (tail_elems > NB) {
        long long rem = tail_elems - NB;
        fill_zero_kernel<<<(int)((rem + 255) / 256), 256>>>(tail + NB, rem);
    }
}